// round 15
// baseline (speedup 1.0000x reference)
#include <cuda_runtime.h>

// Problem constants (from reference setup_inputs)
#define NB 4            // batch
#define EE 16           // embedding dims
#define HW 320000       // 400*800 pixels per image
#define NV (HW / 4)     // float4 groups per plane = 80000
#define CC 20           // label count
#define CK 19           // kept clusters (label 0 = IGNORE)
#define STR 17          // padded stride for [label][e] shared means
#define EB 4            // dim chunks of 4
#define P1_BPP 125      // pass1 blocks per (chunk, batch) plane
#define P1_T 128        // pass1 threads
#define P1_G 5          // groups per thread: 125*128*5 = 80000 = NV exactly
#define P2_BPB 370      // pass2 blocks per batch
#define P2_TOT (P2_BPB * NB)   // 1480 blocks total

// Accumulators (tiny; only 125 REDs per address)
__device__ float4 g_red[CC * EB * NB];
__device__ float g_cnt[NB * CC];
__device__ float g_var[NB * CC];
__device__ unsigned int g_done;     // zero-initialized; reset by final block

__device__ __forceinline__ void red4(float4* p, float4 v) {
    asm volatile("red.global.add.v4.f32 [%0], {%1,%2,%3,%4};"
                 :: "l"(p), "f"(v.x), "f"(v.y), "f"(v.z), "f"(v.w) : "memory");
}

// ---------------------------------------------------------------------------
// Pass 1: per-thread privatized segment sums (unchanged hot loop).
// ---------------------------------------------------------------------------
__device__ __forceinline__ void p1_accum(float4* my, int4 L,
                                         float4 a, float4 b, float4 c, float4 d) {
    float4 t;
    t = my[L.x]; t.x += a.x; t.y += b.x; t.z += c.x; t.w += d.x; my[L.x] = t;
    t = my[L.y]; t.x += a.y; t.y += b.y; t.z += c.y; t.w += d.y; my[L.y] = t;
    t = my[L.z]; t.x += a.z; t.y += b.z; t.z += c.z; t.w += d.z; my[L.z] = t;
    t = my[L.w]; t.x += a.w; t.y += b.w; t.z += c.w; t.w += d.w; my[L.w] = t;
}

__global__ void __launch_bounds__(P1_T) k_pass1(const float* __restrict__ emb,
                                                const int* __restrict__ tgt) {
    const int eb = blockIdx.y;
    const int n  = blockIdx.z;
    const int tid = threadIdx.x;
    const bool docnt = (eb == 0);

    __shared__ float4 sacc[P1_T * (CC + 1)];   // 43008 B
    __shared__ float scnt[4][32];

    float4* my = &sacc[tid * (CC + 1)];
#pragma unroll
    for (int j = 0; j < CC + 1; j++) my[j] = make_float4(0.f, 0.f, 0.f, 0.f);
    if (tid < 4 * 32) (&scnt[0][0])[tid] = 0.f;
    __syncthreads();

    const float4* emb4 = reinterpret_cast<const float4*>(emb);
    const float4* e0 = emb4 + (size_t)(n * EE + eb * 4 + 0) * NV;
    const float4* e1 = emb4 + (size_t)(n * EE + eb * 4 + 1) * NV;
    const float4* e2 = emb4 + (size_t)(n * EE + eb * 4 + 2) * NV;
    const float4* e3 = emb4 + (size_t)(n * EE + eb * 4 + 3) * NV;
    const int4* tgtn = reinterpret_cast<const int4*>(tgt) + (size_t)n * NV;
    float* sc = scnt[tid >> 5];

    const int vbase = blockIdx.x * (P1_T * P1_G) + tid;

#pragma unroll 1
    for (int i = 0; i < P1_G / 2; i++) {
        const int v0 = vbase + (2 * i) * P1_T;
        const int v1 = v0 + P1_T;
        int4 L0 = tgtn[v0], L1 = tgtn[v1];
        float4 a0 = e0[v0], b0 = e1[v0], c0 = e2[v0], d0 = e3[v0];
        float4 a1 = e0[v1], b1 = e1[v1], c1 = e2[v1], d1 = e3[v1];
        if (docnt) {
            atomicAdd(&sc[L0.x], 1.f); atomicAdd(&sc[L0.y], 1.f);
            atomicAdd(&sc[L0.z], 1.f); atomicAdd(&sc[L0.w], 1.f);
            atomicAdd(&sc[L1.x], 1.f); atomicAdd(&sc[L1.y], 1.f);
            atomicAdd(&sc[L1.z], 1.f); atomicAdd(&sc[L1.w], 1.f);
        }
        p1_accum(my, L0, a0, b0, c0, d0);
        p1_accum(my, L1, a1, b1, c1, d1);
    }
    {
        const int v0 = vbase + (P1_G - 1) * P1_T;
        int4 L0 = tgtn[v0];
        float4 a0 = e0[v0], b0 = e1[v0], c0 = e2[v0], d0 = e3[v0];
        if (docnt) {
            atomicAdd(&sc[L0.x], 1.f); atomicAdd(&sc[L0.y], 1.f);
            atomicAdd(&sc[L0.z], 1.f); atomicAdd(&sc[L0.w], 1.f);
        }
        p1_accum(my, L0, a0, b0, c0, d0);
    }

    // tree-reduce 128 -> 16 regions
#pragma unroll
    for (int s = P1_T / 2; s >= 16; s >>= 1) {
        __syncthreads();
        if (tid < s) {
            const float4* other = &sacc[(tid + s) * (CC + 1)];
#pragma unroll
            for (int lab = 0; lab < CC; lab++) {
                float4 t = my[lab], o = other[lab];
                t.x += o.x; t.y += o.y; t.z += o.z; t.w += o.w;
                my[lab] = t;
            }
        }
    }
    __syncthreads();

    if (tid < CC) {
        float4 t = make_float4(0.f, 0.f, 0.f, 0.f);
#pragma unroll
        for (int r = 0; r < 16; r++) {
            float4 o = sacc[r * (CC + 1) + tid];
            t.x += o.x; t.y += o.y; t.z += o.z; t.w += o.w;
        }
        red4(&g_red[(tid * EB + eb) * NB + n], t);
    }

    if (docnt && tid < CC) {
        float t = scnt[0][tid] + scnt[1][tid] + scnt[2][tid] + scnt[3][tid];
        atomicAdd(&g_cnt[n * CC + tid], t);
    }
}

// ---------------------------------------------------------------------------
// Pass 2 (fused): prologue computes means from g_red/g_cnt; main loop is the
// variance hot loop; the LAST finishing block (fence + counter) computes the
// push/reg terms + final combine, writes out[0], and re-zeroes all state.
// ---------------------------------------------------------------------------
__global__ void __launch_bounds__(256, 8) k_pass2(const float* __restrict__ emb,
                                                  const int* __restrict__ tgt,
                                                  float* __restrict__ out) {
    const int n = blockIdx.y;
    __shared__ float m[CC * STR];
    __shared__ float svw[8][CC + 1];
    __shared__ float cnt[CC];
    __shared__ int is_last;
    const int tid = threadIdx.x;

    // prologue: means for this batch from g_red / g_cnt
    if (tid < CC) cnt[tid] = g_cnt[n * CC + tid];
    if (tid == 0) is_last = 0;
    for (int j = tid; j < 8 * (CC + 1); j += blockDim.x) (&svw[0][0])[j] = 0.f;
    __syncthreads();
    {
        const float* redf = reinterpret_cast<const float*>(g_red);
        for (int j = tid; j < CC * EE; j += blockDim.x) {
            int lab = j / EE, e = j % EE;
            float sum = redf[((lab * EB + (e >> 2)) * NB + n) * 4 + (e & 3)];
            m[lab * STR + e] = sum / cnt[lab];
        }
    }
    __syncthreads();
    float* sv = svw[tid >> 5];

    const float4* embn = reinterpret_cast<const float4*>(emb) + (size_t)n * EE * NV;
    const int4*   tgtn = reinterpret_cast<const int4*>(tgt) + (size_t)n * NV;

    for (int v = blockIdx.x * blockDim.x + tid; v < NV;
         v += gridDim.x * blockDim.x) {
        int4 L = tgtn[v];
        int bx = L.x * STR, by = L.y * STR, bz = L.z * STR, bw = L.w * STR;
        float d0 = 0.f, d1 = 0.f, d2 = 0.f, d3 = 0.f;
#pragma unroll
        for (int e = 0; e < EE; e++) {
            float4 x = embn[(size_t)e * NV + v];
            float t0 = x.x - m[bx + e]; d0 = fmaf(t0, t0, d0);
            float t1 = x.y - m[by + e]; d1 = fmaf(t1, t1, d1);
            float t2 = x.z - m[bz + e]; d2 = fmaf(t2, t2, d2);
            float t3 = x.w - m[bw + e]; d3 = fmaf(t3, t3, d3);
        }
        if (L.x != 0) { float d = sqrtf(d0); float h = fmaxf(d - 0.5f, 0.f); atomicAdd(&sv[L.x], h * h); }
        if (L.y != 0) { float d = sqrtf(d1); float h = fmaxf(d - 0.5f, 0.f); atomicAdd(&sv[L.y], h * h); }
        if (L.z != 0) { float d = sqrtf(d2); float h = fmaxf(d - 0.5f, 0.f); atomicAdd(&sv[L.z], h * h); }
        if (L.w != 0) { float d = sqrtf(d3); float h = fmaxf(d - 0.5f, 0.f); atomicAdd(&sv[L.w], h * h); }
    }
    __syncthreads();
    if (tid < CC) {
        float t = 0.f;
#pragma unroll
        for (int w = 0; w < 8; w++) t += svw[w][tid];
        atomicAdd(&g_var[n * CC + tid], t);
    }

    // completion counter: last block performs the final combine
    __syncthreads();
    if (tid == 0) {
        __threadfence();
        unsigned int old = atomicAdd(&g_done, 1u);
        if (old == P2_TOT - 1) is_last = 1;
    }
    __syncthreads();
    if (!is_last) return;

    // ------------------- final combine (one block) -------------------
    __shared__ float fm[NB][CC][EE];     // all-batch means (20.5 KB)
    __shared__ float facc[NB][3];        // per-batch: var, push, reg
    __shared__ float fcnt[NB][CC];

    if (tid < NB * 3) facc[tid / 3][tid % 3] = 0.f;
    for (int j = tid; j < NB * CC; j += blockDim.x)
        fcnt[j / CC][j % CC] = g_cnt[j];
    __syncthreads();

    const float* redf = reinterpret_cast<const float*>(g_red);
    for (int j = tid; j < NB * CC * EE; j += blockDim.x) {
        int nn = j / (CC * EE), r = j % (CC * EE);
        int lab = r / EE, e = r % EE;
        float sum = redf[((lab * EB + (e >> 2)) * NB + nn) * 4 + (e & 3)];
        fm[nn][lab][e] = sum / fcnt[nn][lab];
    }
    __syncthreads();

    // variance term: sum_c g_var/cnt
    if (tid < NB * CK) {
        int nn = tid / CK, c = tid % CK + 1;
        atomicAdd(&facc[nn][0], g_var[nn * CC + c] / fcnt[nn][c]);
    }
    // push term: all (n, i, j) kept pairs
    for (int pr = tid; pr < NB * CK * CK; pr += blockDim.x) {
        int nn = pr / (CK * CK), r = pr % (CK * CK);
        int i = r / CK + 1, j2 = r % CK + 1;
        if (i != j2) {
            float d2 = 0.f;
#pragma unroll
            for (int e = 0; e < EE; e++) {
                float df = fm[nn][i][e] - fm[nn][j2][e];
                d2 += df * df;
            }
            float dm = (d2 > 0.f) ? sqrtf(d2) : 0.f;
            float h = fmaxf(3.0f - dm, 0.f);
            atomicAdd(&facc[nn][1], h * h);
        }
    }
    // regularizer
    if (tid < NB * CK) {
        int nn = tid / CK, c = tid % CK + 1;
        float d2 = 0.f;
#pragma unroll
        for (int e = 0; e < EE; e++) {
            float mv = fm[nn][c][e];
            d2 += mv * mv;
        }
        atomicAdd(&facc[nn][2], (d2 > 0.f) ? sqrtf(d2) : 0.f);
    }
    __syncthreads();

    if (tid == 0) {
        float tot = 0.f;
        for (int nn = 0; nn < NB; nn++)
            tot += facc[nn][0] / (float)CK
                 + facc[nn][1] / (float)(CK * (CK - 1))
                 + 0.001f * facc[nn][2] / (float)CK;
        out[0] = tot / (float)NB;
        g_done = 0u;
    }
    // self-clean for next replay
    {
        const float4 z4 = make_float4(0.f, 0.f, 0.f, 0.f);
        for (int j = tid; j < CC * EB * NB; j += blockDim.x) g_red[j] = z4;
        for (int j = tid; j < NB * CC; j += blockDim.x) { g_cnt[j] = 0.f; g_var[j] = 0.f; }
    }
}

// ---------------------------------------------------------------------------
extern "C" void kernel_launch(void* const* d_in, const int* in_sizes, int n_in,
                              void* d_out, int out_size) {
    const float* emb = (const float*)d_in[0];
    const int*   tgt = (const int*)d_in[1];
    float*       out = (float*)d_out;

    k_pass1<<<dim3(P1_BPP, EB, NB), P1_T>>>(emb, tgt);
    k_pass2<<<dim3(P2_BPB, NB), 256>>>(emb, tgt, out);
}